// round 13
// baseline (speedup 1.0000x reference)
#include <cuda_runtime.h>
#include <math.h>
#include <stdint.h>

#define D_MODEL 1024
#define SEQ     4096
#define BATCH   4
#define NHEAD   16
#define DHEAD   64
#define WIN     512
#define NWIN    (SEQ / WIN)
#define MROWS   (BATCH * SEQ)      // 16384
#define DFF     (4 * D_MODEL)      // 4096
#define QKV_LD  (3 * D_MODEL)      // 3072
#define LN_EPS  1e-5f

// ---------------- scratch (device globals; no runtime allocation) ----------
__device__ float g_srct[(size_t)MROWS * D_MODEL];
__device__ float g_wqkv[(size_t)QKV_LD * D_MODEL];
__device__ float g_bqkv[QKV_LD];
__device__ float g_qkv [(size_t)MROWS * QKV_LD];
__device__ float g_attn[(size_t)MROWS * D_MODEL];
__device__ float g_x1  [(size_t)MROWS * D_MODEL];
__device__ float g_x1t [(size_t)MROWS * D_MODEL];
__device__ float g_w1t [(size_t)DFF * D_MODEL];
__device__ float g_ffnt[(size_t)MROWS * DFF];
__device__ float g_w2t [(size_t)D_MODEL * DFF];
__device__ float g_f2  [(size_t)MROWS * D_MODEL];

// ---------------- PTX helpers ----------------------------------------------
__device__ __forceinline__ uint32_t smem_u32(const void* p) {
    uint32_t a;
    asm("{ .reg .u64 t; cvta.to.shared.u64 t, %1; cvt.u32.u64 %0, t; }"
        : "=r"(a) : "l"(p));
    return a;
}

__device__ __forceinline__ float f32_to_tf32(float x) {
    uint32_t u;
    asm("cvt.rna.tf32.f32 %0, %1;" : "=r"(u) : "f"(x));
    return __uint_as_float(u);
}

#define CP_ASYNC16(dst, src) \
    asm volatile("cp.async.cg.shared.global [%0], [%1], 16;" :: "r"(dst), "l"(src))
#define CP_COMMIT() asm volatile("cp.async.commit_group;" ::: "memory")

__device__ __forceinline__ void ldsm_x4(uint32_t& r0, uint32_t& r1, uint32_t& r2,
                                        uint32_t& r3, uint32_t addr) {
    asm volatile("ldmatrix.sync.aligned.m8n8.x4.shared.b16 {%0,%1,%2,%3}, [%4];"
                 : "=r"(r0), "=r"(r1), "=r"(r2), "=r"(r3) : "r"(addr));
}

__device__ __forceinline__ void mma8(float* c, const uint32_t* a, const uint32_t* b) {
    asm volatile(
        "mma.sync.aligned.m16n8k8.row.col.f32.tf32.tf32.f32 "
        "{%0,%1,%2,%3}, {%4,%5,%6,%7}, {%8,%9}, {%0,%1,%2,%3};"
        : "+f"(c[0]), "+f"(c[1]), "+f"(c[2]), "+f"(c[3])
        : "r"(a[0]), "r"(a[1]), "r"(a[2]), "r"(a[3]), "r"(b[0]), "r"(b[1]));
}

// ---------------- tf32 mma.sync GEMM: C = A[M,K] @ B[N,K]^T + bias ----------
// CTA 128x128x32, 128 threads (4 warps, 2x2), warp tile 64x64.
// 3-stage cp.async ring, one __syncthreads per k-iter.
// MODE: 0 = plain, 1 = relu + tf32 round, 2 = tf32 round
#define GSTG 3
#define STAGE_B (128 * 128 * 2)
#define GEMM_SMEM (GSTG * STAGE_B)

template <int MODE>
__global__ void __launch_bounds__(128, 2)
gemm_mma(const float* __restrict__ A, const float* __restrict__ B,
         const float* __restrict__ bias, float* __restrict__ C,
         int K, int ldC) {
    extern __shared__ char smraw[];
    const uint32_t sbase = smem_u32(smraw);

    const int tid = threadIdx.x;
    const int lane = tid & 31;
    const int w = tid >> 5;                       // 0..3
    const int m0 = blockIdx.y * 128, n0 = blockIdx.x * 128;
    const int wm = (w & 1) * 64, wn = (w >> 1) * 64;
    const int KT = K >> 5;

    // loader: thread owns A row tid and B row tid
    const float* gA = A + (size_t)(m0 + tid) * K;
    const float* gB = B + (size_t)(n0 + tid) * K;
    const uint32_t dstA = sbase + (uint32_t)tid * 128u;
    const uint32_t dstB = sbase + 16384u + (uint32_t)tid * 128u;
    const uint32_t swz = (uint32_t)(tid & 7);

    float acc[4][8][4];
#pragma unroll
    for (int i = 0; i < 4; i++)
#pragma unroll
        for (int j = 0; j < 8; j++)
#pragma unroll
            for (int r = 0; r < 4; r++) acc[i][j][r] = 0.f;

    // prologue: stages 0 and 1
#pragma unroll
    for (int s = 0; s < 2; s++) {
        const uint32_t so = (uint32_t)s * STAGE_B;
#pragma unroll
        for (int c = 0; c < 8; c++) {
            const uint32_t o = (((uint32_t)c ^ swz) << 4);
            CP_ASYNC16(dstA + so + o, gA + s * 32 + c * 4);
            CP_ASYNC16(dstB + so + o, gB + s * 32 + c * 4);
        }
        CP_COMMIT();
    }

    const int g = lane >> 3, lr = lane & 7;
    uint32_t aRow[4], bRow[4];
#pragma unroll
    for (int i = 0; i < 4; i++) aRow[i] = (uint32_t)(wm + i * 16 + (g & 1) * 8 + lr);
#pragma unroll
    for (int p = 0; p < 4; p++) bRow[p] = (uint32_t)(wn + p * 16 + (g >> 1) * 8 + lr);
    const uint32_t aU = (uint32_t)(g >> 1);
    const uint32_t bU = (uint32_t)(g & 1);

    for (int i = 0; i < KT; i++) {
        asm volatile("cp.async.wait_group 1;" ::: "memory");
        __syncthreads();
        if (i + 2 < KT) {
            const uint32_t so = (uint32_t)((i + 2) % GSTG) * STAGE_B;
            const float* pa = gA + (i + 2) * 32;
            const float* pb = gB + (i + 2) * 32;
#pragma unroll
            for (int c = 0; c < 8; c++) {
                const uint32_t o = (((uint32_t)c ^ swz) << 4);
                CP_ASYNC16(dstA + so + o, pa + c * 4);
                CP_ASYNC16(dstB + so + o, pb + c * 4);
            }
        }
        CP_COMMIT();

        const uint32_t sa = sbase + (uint32_t)(i % GSTG) * STAGE_B;
        const uint32_t sb = sa + 16384u;
#pragma unroll
        for (int ks = 0; ks < 4; ks++) {
            uint32_t a[4][4], bf[8][2];
#pragma unroll
            for (int t = 0; t < 4; t++) {
                const uint32_t r = aRow[t];
                const uint32_t addr = sa + r * 128u + (((2u * ks + aU) ^ (r & 7u)) << 4);
                ldsm_x4(a[t][0], a[t][1], a[t][2], a[t][3], addr);
            }
#pragma unroll
            for (int p = 0; p < 4; p++) {
                const uint32_t r = bRow[p];
                const uint32_t addr = sb + r * 128u + (((2u * ks + bU) ^ (r & 7u)) << 4);
                ldsm_x4(bf[2 * p][0], bf[2 * p][1], bf[2 * p + 1][0], bf[2 * p + 1][1], addr);
            }
#pragma unroll
            for (int mt = 0; mt < 4; mt++)
#pragma unroll
                for (int nt = 0; nt < 8; nt++) mma8(acc[mt][nt], a[mt], bf[nt]);
        }
    }

    const int qr = lane >> 2;
    const int qc = 2 * (lane & 3);
#pragma unroll
    for (int mt = 0; mt < 4; mt++) {
        const int row0 = m0 + wm + mt * 16 + qr;
#pragma unroll
        for (int nt = 0; nt < 8; nt++) {
            const int col = n0 + wn + nt * 8 + qc;
            const float2 bv = *(const float2*)&bias[col];
#pragma unroll
            for (int h = 0; h < 2; h++) {
                float v0 = acc[mt][nt][2 * h + 0] + bv.x;
                float v1 = acc[mt][nt][2 * h + 1] + bv.y;
                if (MODE == 1) {
                    v0 = f32_to_tf32(fmaxf(v0, 0.f));
                    v1 = f32_to_tf32(fmaxf(v1, 0.f));
                } else if (MODE == 2) {
                    v0 = f32_to_tf32(v0);
                    v1 = f32_to_tf32(v1);
                }
                float2 o; o.x = v0; o.y = v1;
                *(float2*)&C[(size_t)(row0 + 8 * h) * ldC + col] = o;
            }
        }
    }
}

// ---------------- conversion kernels ---------------------------------------
__global__ void cvt_tf32_kernel(const float* __restrict__ in, float* __restrict__ out, int n4) {
    int i = blockIdx.x * blockDim.x + threadIdx.x;
    if (i < n4) {
        float4 v = ((const float4*)in)[i];
        v.x = f32_to_tf32(v.x); v.y = f32_to_tf32(v.y);
        v.z = f32_to_tf32(v.z); v.w = f32_to_tf32(v.w);
        ((float4*)out)[i] = v;
    }
}

__global__ void cvt_wqkv_kernel(const float* __restrict__ wq, const float* __restrict__ wk,
                                const float* __restrict__ wv, float* __restrict__ out) {
    const int seg = D_MODEL * D_MODEL / 4;
    int i = blockIdx.x * blockDim.x + threadIdx.x;
    if (i < 3 * seg) {
        const float* src = (i < seg) ? wq : (i < 2 * seg) ? wk : wv;
        int j = (i < seg) ? i : (i < 2 * seg) ? i - seg : i - 2 * seg;
        float4 v = ((const float4*)src)[j];
        v.x = f32_to_tf32(v.x); v.y = f32_to_tf32(v.y);
        v.z = f32_to_tf32(v.z); v.w = f32_to_tf32(v.w);
        ((float4*)out)[i] = v;
    }
}

__global__ void bias_concat_kernel(const float* bq, const float* bk, const float* bv,
                                   float* out) {
    int i = blockIdx.x * blockDim.x + threadIdx.x;
    if (i < QKV_LD) {
        float v;
        if (i < D_MODEL) v = bq[i];
        else if (i < 2 * D_MODEL) v = bk[i - D_MODEL];
        else v = bv[i - 2 * D_MODEL];
        out[i] = v;
    }
}

// ---------------- tensor-core local attention -------------------------------
// block = 256 thr (8 warps), 128 q-rows/block, 64 kv/iter, d=64.
#define AQ_PLANE 16384
#define AK_PLANE 8192
#define ATT_SMEM (96 * 1024)

__global__ void __launch_bounds__(256)
attn_mma(const float* __restrict__ QKV, float* __restrict__ Og) {
    extern __shared__ char araw[];
    const uint32_t sb = smem_u32(araw);
    const uint32_t Qs = sb;
    const uint32_t Ks = sb + 32768u;
    const uint32_t Vt = sb + 49152u;
    const uint32_t Ps = sb + 65536u;

    const int tid = threadIdx.x;
    const int lane = tid & 31;
    const int w = tid >> 5;
    const int qt = blockIdx.x;
    const int wnd = blockIdx.y, bh = blockIdx.z;
    const int b = bh >> 4, h = bh & 15;
    const int q0 = wnd * WIN + qt * 128;
    const size_t base = (size_t)b * SEQ * QKV_LD + (size_t)h * DHEAD;
    const size_t obase = (size_t)b * SEQ * D_MODEL + (size_t)h * DHEAD;

    {
        const int r = tid >> 1, half = tid & 1;
        const float* src = QKV + base + (size_t)(q0 + r) * QKV_LD + half * 32;
        const uint32_t drow = Qs + (uint32_t)half * AQ_PLANE + (uint32_t)r * 128u;
#pragma unroll
        for (int u = 0; u < 8; u++) {
            float4 v = *(const float4*)(src + u * 4);
            uint32_t addr = drow + ((uint32_t)(u ^ (r & 7)) << 4);
            asm volatile("st.shared.v4.b32 [%0], {%1,%2,%3,%4};"
                         :: "r"(addr), "r"(__float_as_uint(v.x)), "r"(__float_as_uint(v.y)),
                            "r"(__float_as_uint(v.z)), "r"(__float_as_uint(v.w)) : "memory");
        }
    }

    const int g = lane >> 3, lr = lane & 7;
    const uint32_t aRow = (uint32_t)(w * 16 + (g & 1) * 8 + lr);
    const uint32_t aU = (uint32_t)(g >> 1);
    const uint32_t bU = (uint32_t)(g & 1);
    uint32_t bRow[4];
#pragma unroll
    for (int p = 0; p < 4; p++) bRow[p] = (uint32_t)(p * 16 + (g >> 1) * 8 + lr);

    float acc[8][4];
#pragma unroll
    for (int nt = 0; nt < 8; nt++)
#pragma unroll
        for (int r = 0; r < 4; r++) acc[nt][r] = 0.f;
    float mi0 = -INFINITY, mi1 = -INFINITY, li0 = 0.f, li1 = 0.f;

    const int qrow0 = q0 + w * 16 + (lane >> 2);
    const int qrow1 = qrow0 + 8;
    const int qmax = q0 + w * 16 + 15;

    const int cstart = (wnd == 0) ? 8 : 0;
    const int cend = 2 * qt + 10;

    for (int c = cstart; c < cend; c++) {
        const int kbase = (wnd - 1) * WIN + c * 64;
        __syncthreads();
        if (tid < 128) {
            const int r = tid >> 1, half = tid & 1;
            const float* ks = QKV + base + D_MODEL + (size_t)(kbase + r) * QKV_LD + half * 32;
            const uint32_t drow = Ks + (uint32_t)half * AK_PLANE + (uint32_t)r * 128u;
#pragma unroll
            for (int u = 0; u < 8; u++) {
                float4 v = *(const float4*)(ks + u * 4);
                uint32_t addr = drow + ((uint32_t)(u ^ (r & 7)) << 4);
                asm volatile("st.shared.v4.b32 [%0], {%1,%2,%3,%4};"
                             :: "r"(addr), "r"(__float_as_uint(v.x)), "r"(__float_as_uint(v.y)),
                                "r"(__float_as_uint(v.z)), "r"(__float_as_uint(v.w)) : "memory");
            }
        } else {
            const int t = tid - 128;
            const int r = t >> 1, half = t & 1;
            const float* vs = QKV + base + 2 * D_MODEL + (size_t)(kbase + r) * QKV_LD + half * 32;
            const uint32_t vplane = Vt + (uint32_t)(r >> 5) * AK_PLANE;
            const uint32_t kunit = (uint32_t)((r & 31) >> 2);
            const uint32_t kpos = (uint32_t)(r & 3) * 4u;
#pragma unroll
            for (int u = 0; u < 8; u++) {
                float4 v = *(const float4*)(vs + u * 4);
                const int d0 = half * 32 + u * 4;
#pragma unroll
                for (int e = 0; e < 4; e++) {
                    const uint32_t dr = (uint32_t)(d0 + e);
                    uint32_t addr = vplane + dr * 128u + ((kunit ^ (dr & 7u)) << 4) + kpos;
                    asm volatile("st.shared.b32 [%0], %1;"
                                 :: "r"(addr), "r"(__float_as_uint((&v.x)[e])) : "memory");
                }
            }
        }
        __syncthreads();

        if (kbase > qmax) continue;

        float sc[8][4];
#pragma unroll
        for (int nt = 0; nt < 8; nt++)
#pragma unroll
            for (int r = 0; r < 4; r++) sc[nt][r] = 0.f;
#pragma unroll
        for (int ks = 0; ks < 8; ks++) {
            const uint32_t qpl = Qs + (uint32_t)(ks >> 2) * AQ_PLANE;
            const uint32_t kpl = Ks + (uint32_t)(ks >> 2) * AK_PLANE;
            const uint32_t un = (uint32_t)(ks & 3) * 2u;
            uint32_t a[4], bf[8][2];
            {
                uint32_t addr = qpl + aRow * 128u + (((un + aU) ^ (aRow & 7u)) << 4);
                ldsm_x4(a[0], a[1], a[2], a[3], addr);
            }
#pragma unroll
            for (int p = 0; p < 4; p++) {
                uint32_t addr = kpl + bRow[p] * 128u + (((un + bU) ^ (bRow[p] & 7u)) << 4);
                ldsm_x4(bf[2 * p][0], bf[2 * p][1], bf[2 * p + 1][0], bf[2 * p + 1][1], addr);
            }
#pragma unroll
            for (int nt = 0; nt < 8; nt++) mma8(sc[nt], a, bf[nt]);
        }

        float rm0 = -INFINITY, rm1 = -INFINITY;
#pragma unroll
        for (int nt = 0; nt < 8; nt++) {
            const int col = kbase + nt * 8 + 2 * (lane & 3);
            sc[nt][0] = (col     <= qrow0) ? sc[nt][0] * 0.125f : -INFINITY;
            sc[nt][1] = (col + 1 <= qrow0) ? sc[nt][1] * 0.125f : -INFINITY;
            sc[nt][2] = (col     <= qrow1) ? sc[nt][2] * 0.125f : -INFINITY;
            sc[nt][3] = (col + 1 <= qrow1) ? sc[nt][3] * 0.125f : -INFINITY;
            rm0 = fmaxf(rm0, fmaxf(sc[nt][0], sc[nt][1]));
            rm1 = fmaxf(rm1, fmaxf(sc[nt][2], sc[nt][3]));
        }
#pragma unroll
        for (int o = 1; o <= 2; o <<= 1) {
            rm0 = fmaxf(rm0, __shfl_xor_sync(0xffffffffu, rm0, o));
            rm1 = fmaxf(rm1, __shfl_xor_sync(0xffffffffu, rm1, o));
        }
        const float mn0 = fmaxf(mi0, rm0), mn1 = fmaxf(mi1, rm1);
        const float co0 = (mn0 != -INFINITY) ? __expf(mi0 - mn0) : 0.f;
        const float co1 = (mn1 != -INFINITY) ? __expf(mi1 - mn1) : 0.f;
        float rs0 = 0.f, rs1 = 0.f;
        const uint32_t prow0 = (uint32_t)(w * 16 + (lane >> 2));
#pragma unroll
        for (int nt = 0; nt < 8; nt++) {
            float e0 = (sc[nt][0] != -INFINITY) ? __expf(sc[nt][0] - mn0) : 0.f;
            float e1 = (sc[nt][1] != -INFINITY) ? __expf(sc[nt][1] - mn0) : 0.f;
            float e2 = (sc[nt][2] != -INFINITY) ? __expf(sc[nt][2] - mn1) : 0.f;
            float e3 = (sc[nt][3] != -INFINITY) ? __expf(sc[nt][3] - mn1) : 0.f;
            rs0 += e0 + e1; rs1 += e2 + e3;
            const uint32_t cl = (uint32_t)(nt * 8 + 2 * (lane & 3));
            const uint32_t pl = Ps + (cl >> 5) * AQ_PLANE;
            const uint32_t uoff = (((cl & 31) >> 2) << 4);
            const uint32_t ppos = (cl & 3) * 4u;
            uint32_t a0 = pl + prow0 * 128u + (uoff ^ ((prow0 & 7u) << 4)) + ppos;
            uint32_t a1 = pl + (prow0 + 8u) * 128u + (uoff ^ (((prow0 + 8u) & 7u) << 4)) + ppos;
            asm volatile("st.shared.v2.b32 [%0], {%1,%2};"
                         :: "r"(a0), "r"(__float_as_uint(f32_to_tf32(e0))),
                            "r"(__float_as_uint(f32_to_tf32(e1))) : "memory");
            asm volatile("st.shared.v2.b32 [%0], {%1,%2};"
                         :: "r"(a1), "r"(__float_as_uint(f32_to_tf32(e2))),
                            "r"(__float_as_uint(f32_to_tf32(e3))) : "memory");
        }
#pragma unroll
        for (int o = 1; o <= 2; o <<= 1) {
            rs0 += __shfl_xor_sync(0xffffffffu, rs0, o);
            rs1 += __shfl_xor_sync(0xffffffffu, rs1, o);
        }
        li0 = li0 * co0 + rs0; li1 = li1 * co1 + rs1;
        mi0 = mn0; mi1 = mn1;
#pragma unroll
        for (int nt = 0; nt < 8; nt++) {
            acc[nt][0] *= co0; acc[nt][1] *= co0;
            acc[nt][2] *= co1; acc[nt][3] *= co1;
        }
        __syncwarp();

#pragma unroll
        for (int ks = 0; ks < 8; ks++) {
            const uint32_t ppl = Ps + (uint32_t)(ks >> 2) * AQ_PLANE;
            const uint32_t vpl = Vt + (uint32_t)(ks >> 2) * AK_PLANE;
            const uint32_t un = (uint32_t)(ks & 3) * 2u;
            uint32_t a[4], bf[8][2];
            {
                uint32_t addr = ppl + aRow * 128u + (((un + aU) ^ (aRow & 7u)) << 4);
                ldsm_x4(a[0], a[1], a[2], a[3], addr);
            }
#pragma unroll
            for (int p = 0; p < 4; p++) {
                uint32_t addr = vpl + bRow[p] * 128u + (((un + bU) ^ (bRow[p] & 7u)) << 4);
                ldsm_x4(bf[2 * p][0], bf[2 * p][1], bf[2 * p + 1][0], bf[2 * p + 1][1], addr);
            }
#pragma unroll
            for (int nt = 0; nt < 8; nt++) mma8(acc[nt], a, bf[nt]);
        }
    }

    const float iv0 = 1.f / li0, iv1 = 1.f / li1;
#pragma unroll
    for (int nt = 0; nt < 8; nt++) {
        const int col = nt * 8 + 2 * (lane & 3);
        float2 o0, o1;
        o0.x = acc[nt][0] * iv0; o0.y = acc[nt][1] * iv0;
        o1.x = acc[nt][2] * iv1; o1.y = acc[nt][3] * iv1;
        *(float2*)&Og[obase + (size_t)qrow0 * D_MODEL + col] = o0;
        *(float2*)&Og[obase + (size_t)qrow1 * D_MODEL + col] = o1;
    }
}

// ---------------- fused residual + layernorm --------------------------------
template <int WRITE_T>
__global__ void __launch_bounds__(256)
ln_kernel(const float* __restrict__ A, const float* __restrict__ Badd,
          float aScale, const float* __restrict__ g, const float* __restrict__ be,
          float* __restrict__ out, float* __restrict__ out_t) {
    const int row = blockIdx.x;
    const int tid = threadIdx.x;
    const size_t off = (size_t)row * D_MODEL;

    float y[4];
    float s = 0.f, s2 = 0.f;
#pragma unroll
    for (int u = 0; u < 4; u++) {
        const int c = tid + u * 256;
        float v = aScale * A[off + c];
        if (Badd) v += Badd[off + c];
        y[u] = v;
        s += v;
        s2 += v * v;
    }
#pragma unroll
    for (int o = 16; o; o >>= 1) {
        s  += __shfl_xor_sync(0xffffffffu, s, o);
        s2 += __shfl_xor_sync(0xffffffffu, s2, o);
    }
    __shared__ float rs[8], rs2[8];
    __shared__ float sh_mu, sh_rstd;
    const int wid = tid >> 5, lane = tid & 31;
    if (lane == 0) { rs[wid] = s; rs2[wid] = s2; }
    __syncthreads();
    if (tid == 0) {
        float S = 0.f, S2 = 0.f;
#pragma unroll
        for (int i = 0; i < 8; i++) { S += rs[i]; S2 += rs2[i]; }
        const float mu = S * (1.f / D_MODEL);
        const float var = S2 * (1.f / D_MODEL) - mu * mu;
        sh_mu = mu;
        sh_rstd = rsqrtf(var + LN_EPS);
    }
    __syncthreads();
    const float mu = sh_mu, rstd = sh_rstd;
#pragma unroll
    for (int u = 0; u < 4; u++) {
        const int c = tid + u * 256;
        const float v = (y[u] - mu) * rstd * g[c] + be[c];
        out[off + c] = v;
        if (WRITE_T) out_t[off + c] = f32_to_tf32(v);
    }
}

// ---------------- launch ----------------------------------------------------
extern "C" void kernel_launch(void* const* d_in, const int* in_sizes, int n_in,
                              void* d_out, int out_size) {
    const float* src = (const float*)d_in[0];
    const float* wq = (const float*)d_in[1];  const float* bq = (const float*)d_in[2];
    const float* wk = (const float*)d_in[3];  const float* bk = (const float*)d_in[4];
    const float* wv = (const float*)d_in[5];  const float* bv = (const float*)d_in[6];
    const float* w1 = (const float*)d_in[7];  const float* b1 = (const float*)d_in[8];
    const float* w2 = (const float*)d_in[9];  const float* b2 = (const float*)d_in[10];
    const float* g1 = (const float*)d_in[11]; const float* be1 = (const float*)d_in[12];
    const float* g2 = (const float*)d_in[13]; const float* be2 = (const float*)d_in[14];
    float* out = (float*)d_out;

    void *psrct, *pwqkv, *pbqkv, *pqkv, *pattn, *px1, *px1t, *pw1t, *pffnt, *pw2t, *pf2;
    cudaGetSymbolAddress(&psrct, g_srct);
    cudaGetSymbolAddress(&pwqkv, g_wqkv);
    cudaGetSymbolAddress(&pbqkv, g_bqkv);
    cudaGetSymbolAddress(&pqkv,  g_qkv);
    cudaGetSymbolAddress(&pattn, g_attn);
    cudaGetSymbolAddress(&px1,   g_x1);
    cudaGetSymbolAddress(&px1t,  g_x1t);
    cudaGetSymbolAddress(&pw1t,  g_w1t);
    cudaGetSymbolAddress(&pffnt, g_ffnt);
    cudaGetSymbolAddress(&pw2t,  g_w2t);
    cudaGetSymbolAddress(&pf2,   g_f2);

    cudaFuncSetAttribute(gemm_mma<0>, cudaFuncAttributeMaxDynamicSharedMemorySize, GEMM_SMEM);
    cudaFuncSetAttribute(gemm_mma<1>, cudaFuncAttributeMaxDynamicSharedMemorySize, GEMM_SMEM);
    cudaFuncSetAttribute(gemm_mma<2>, cudaFuncAttributeMaxDynamicSharedMemorySize, GEMM_SMEM);
    cudaFuncSetAttribute(attn_mma, cudaFuncAttributeMaxDynamicSharedMemorySize, ATT_SMEM);

    {   // [0] src -> tf32
        int n4 = MROWS * D_MODEL / 4;
        cvt_tf32_kernel<<<(n4 + 255) / 256, 256>>>(src, (float*)psrct, n4);
    }
    {   // [1] wq|wk|wv -> tf32 concat
        int n4 = 3 * D_MODEL * D_MODEL / 4;
        cvt_wqkv_kernel<<<(n4 + 255) / 256, 256>>>(wq, wk, wv, (float*)pwqkv);
    }
    // [2] bias concat
    bias_concat_kernel<<<(QKV_LD + 255) / 256, 256>>>(bq, bk, bv, (float*)pbqkv);
    {   // [3] w1 -> tf32
        int n4 = DFF * D_MODEL / 4;
        cvt_tf32_kernel<<<(n4 + 255) / 256, 256>>>(w1, (float*)pw1t, n4);
    }
    {   // [4] fused QKV GEMM (epilogue rounds to tf32 for attention)
        dim3 grid(QKV_LD / 128, MROWS / 128);
        gemm_mma<2><<<grid, 128, GEMM_SMEM>>>((const float*)psrct, (const float*)pwqkv,
                                              (const float*)pbqkv, (float*)pqkv,
                                              D_MODEL, QKV_LD);
    }
    {   // [5] tensor-core local attention
        dim3 gAttn(WIN / 128, NWIN, BATCH * NHEAD);
        attn_mma<<<gAttn, 256, ATT_SMEM>>>((const float*)pqkv, (float*)pattn);
    }
    {   // [6] w2 -> tf32
        int n4 = D_MODEL * DFF / 4;
        cvt_tf32_kernel<<<(n4 + 255) / 256, 256>>>(w2, (float*)pw2t, n4);
    }
    // [7] LN1
    ln_kernel<1><<<MROWS, 256>>>((const float*)pattn, nullptr, 2.0f, g1, be1,
                                 (float*)px1, (float*)px1t);
    {   // [8] FFN1
        dim3 grid(DFF / 128, MROWS / 128);
        gemm_mma<1><<<grid, 128, GEMM_SMEM>>>((const float*)px1t, (const float*)pw1t,
                                              b1, (float*)pffnt, D_MODEL, DFF);
    }
    {   // [9] FFN2
        dim3 grid(D_MODEL / 128, MROWS / 128);
        gemm_mma<0><<<grid, 128, GEMM_SMEM>>>((const float*)pffnt, (const float*)pw2t,
                                              b2, (float*)pf2, DFF, D_MODEL);
    }
    // [10] LN2
    ln_kernel<0><<<MROWS, 256>>>((const float*)px1, (const float*)pf2, 1.0f, g2, be2,
                                 out, nullptr);
}

// round 14
// speedup vs baseline: 1.0336x; 1.0336x over previous
#include <cuda_runtime.h>
#include <math.h>
#include <stdint.h>

#define D_MODEL 1024
#define SEQ     4096
#define BATCH   4
#define NHEAD   16
#define DHEAD   64
#define WIN     512
#define NWIN    (SEQ / WIN)
#define MROWS   (BATCH * SEQ)      // 16384
#define DFF     (4 * D_MODEL)      // 4096
#define QKV_LD  (3 * D_MODEL)      // 3072
#define LN_EPS  1e-5f

// ---------------- scratch (device globals; no runtime allocation) ----------
__device__ float g_srct[(size_t)MROWS * D_MODEL];
__device__ float g_wqkv[(size_t)QKV_LD * D_MODEL];
__device__ float g_bqkv[QKV_LD];
__device__ float g_qkv [(size_t)MROWS * QKV_LD];
__device__ float g_attn[(size_t)MROWS * D_MODEL];
__device__ float g_x1  [(size_t)MROWS * D_MODEL];
__device__ float g_x1t [(size_t)MROWS * D_MODEL];
__device__ float g_w1t [(size_t)DFF * D_MODEL];
__device__ float g_ffnt[(size_t)MROWS * DFF];
__device__ float g_w2t [(size_t)D_MODEL * DFF];
__device__ float g_f2  [(size_t)MROWS * D_MODEL];

// ---------------- PTX helpers ----------------------------------------------
__device__ __forceinline__ uint32_t smem_u32(const void* p) {
    uint32_t a;
    asm("{ .reg .u64 t; cvta.to.shared.u64 t, %1; cvt.u32.u64 %0, t; }"
        : "=r"(a) : "l"(p));
    return a;
}

__device__ __forceinline__ float f32_to_tf32(float x) {
    uint32_t u;
    asm("cvt.rna.tf32.f32 %0, %1;" : "=r"(u) : "f"(x));
    return __uint_as_float(u);
}

#define CP_ASYNC16(dst, src) \
    asm volatile("cp.async.cg.shared.global [%0], [%1], 16;" :: "r"(dst), "l"(src))
#define CP_COMMIT() asm volatile("cp.async.commit_group;" ::: "memory")

__device__ __forceinline__ void ldsm_x4(uint32_t& r0, uint32_t& r1, uint32_t& r2,
                                        uint32_t& r3, uint32_t addr) {
    asm volatile("ldmatrix.sync.aligned.m8n8.x4.shared.b16 {%0,%1,%2,%3}, [%4];"
                 : "=r"(r0), "=r"(r1), "=r"(r2), "=r"(r3) : "r"(addr));
}

__device__ __forceinline__ void mma8(float* c, const uint32_t* a, const uint32_t* b) {
    asm volatile(
        "mma.sync.aligned.m16n8k8.row.col.f32.tf32.tf32.f32 "
        "{%0,%1,%2,%3}, {%4,%5,%6,%7}, {%8,%9}, {%0,%1,%2,%3};"
        : "+f"(c[0]), "+f"(c[1]), "+f"(c[2]), "+f"(c[3])
        : "r"(a[0]), "r"(a[1]), "r"(a[2]), "r"(a[3]), "r"(b[0]), "r"(b[1]));
}

// ---------------- tf32 mma.sync GEMM: C = A[M,K] @ B[N,K]^T + bias ----------
// CTA 128x128x32, 128 threads (4 warps, 2x2), warp tile 64x64.
// 3-stage cp.async ring; fragment double-buffering inside the k-iter.
// MODE: 0 = plain, 1 = relu + tf32 round, 2 = tf32 round
#define GSTG 3
#define STAGE_B (128 * 128 * 2)
#define GEMM_SMEM (GSTG * STAGE_B)

__device__ __forceinline__ void frag_load(uint32_t (*a)[4], uint32_t (*bf)[2],
                                          uint32_t sa, uint32_t sb, uint32_t ks,
                                          const uint32_t* aRow, const uint32_t* bRow,
                                          uint32_t aU, uint32_t bU) {
#pragma unroll
    for (int t = 0; t < 4; t++) {
        const uint32_t r = aRow[t];
        ldsm_x4(a[t][0], a[t][1], a[t][2], a[t][3],
                sa + r * 128u + (((2u * ks + aU) ^ (r & 7u)) << 4));
    }
#pragma unroll
    for (int p = 0; p < 4; p++) {
        const uint32_t r = bRow[p];
        ldsm_x4(bf[2 * p][0], bf[2 * p][1], bf[2 * p + 1][0], bf[2 * p + 1][1],
                sb + r * 128u + (((2u * ks + bU) ^ (r & 7u)) << 4));
    }
}

__device__ __forceinline__ void mma_all(float (*acc)[8][4], uint32_t (*a)[4],
                                        uint32_t (*bf)[2]) {
#pragma unroll
    for (int mt = 0; mt < 4; mt++)
#pragma unroll
        for (int nt = 0; nt < 8; nt++) mma8(acc[mt][nt], a[mt], bf[nt]);
}

template <int MODE>
__global__ void __launch_bounds__(128, 2)
gemm_mma(const float* __restrict__ A, const float* __restrict__ B,
         const float* __restrict__ bias, float* __restrict__ C,
         int K, int ldC) {
    extern __shared__ char smraw[];
    const uint32_t sbase = smem_u32(smraw);

    const int tid = threadIdx.x;
    const int lane = tid & 31;
    const int w = tid >> 5;                       // 0..3
    const int m0 = blockIdx.y * 128, n0 = blockIdx.x * 128;
    const int wm = (w & 1) * 64, wn = (w >> 1) * 64;
    const int KT = K >> 5;

    const float* gA = A + (size_t)(m0 + tid) * K;
    const float* gB = B + (size_t)(n0 + tid) * K;
    const uint32_t dstA = sbase + (uint32_t)tid * 128u;
    const uint32_t dstB = sbase + 16384u + (uint32_t)tid * 128u;
    const uint32_t swz = (uint32_t)(tid & 7);

    float acc[4][8][4];
#pragma unroll
    for (int i = 0; i < 4; i++)
#pragma unroll
        for (int j = 0; j < 8; j++)
#pragma unroll
            for (int r = 0; r < 4; r++) acc[i][j][r] = 0.f;

    // prologue: stages 0 and 1
#pragma unroll
    for (int s = 0; s < 2; s++) {
        const uint32_t so = (uint32_t)s * STAGE_B;
#pragma unroll
        for (int c = 0; c < 8; c++) {
            const uint32_t o = (((uint32_t)c ^ swz) << 4);
            CP_ASYNC16(dstA + so + o, gA + s * 32 + c * 4);
            CP_ASYNC16(dstB + so + o, gB + s * 32 + c * 4);
        }
        CP_COMMIT();
    }

    const int g = lane >> 3, lr = lane & 7;
    uint32_t aRow[4], bRow[4];
#pragma unroll
    for (int i = 0; i < 4; i++) aRow[i] = (uint32_t)(wm + i * 16 + (g & 1) * 8 + lr);
#pragma unroll
    for (int p = 0; p < 4; p++) bRow[p] = (uint32_t)(wn + p * 16 + (g >> 1) * 8 + lr);
    const uint32_t aU = (uint32_t)(g >> 1);
    const uint32_t bU = (uint32_t)(g & 1);

    uint32_t af0[4][4], bf0[8][2], af1[4][4], bf1[8][2];

    for (int i = 0; i < KT; i++) {
        asm volatile("cp.async.wait_group 1;" ::: "memory");
        __syncthreads();

        const uint32_t sa = sbase + (uint32_t)(i % GSTG) * STAGE_B;
        const uint32_t sb = sa + 16384u;

        // kick the mma-critical path first: fragments for kslice 0
        frag_load(af0, bf0, sa, sb, 0u, aRow, bRow, aU, bU);

        // then issue the next-stage global loads (overlaps with compute below)
        if (i + 2 < KT) {
            const uint32_t so = (uint32_t)((i + 2) % GSTG) * STAGE_B;
            const float* pa = gA + (i + 2) * 32;
            const float* pb = gB + (i + 2) * 32;
#pragma unroll
            for (int c = 0; c < 8; c++) {
                const uint32_t o = (((uint32_t)c ^ swz) << 4);
                CP_ASYNC16(dstA + so + o, pa + c * 4);
                CP_ASYNC16(dstB + so + o, pb + c * 4);
            }
        }
        CP_COMMIT();

        // software-pipelined kslices: prefetch next while mma current
        frag_load(af1, bf1, sa, sb, 1u, aRow, bRow, aU, bU);
        mma_all(acc, af0, bf0);
        frag_load(af0, bf0, sa, sb, 2u, aRow, bRow, aU, bU);
        mma_all(acc, af1, bf1);
        frag_load(af1, bf1, sa, sb, 3u, aRow, bRow, aU, bU);
        mma_all(acc, af0, bf0);
        mma_all(acc, af1, bf1);
    }

    const int qr = lane >> 2;
    const int qc = 2 * (lane & 3);
#pragma unroll
    for (int mt = 0; mt < 4; mt++) {
        const int row0 = m0 + wm + mt * 16 + qr;
#pragma unroll
        for (int nt = 0; nt < 8; nt++) {
            const int col = n0 + wn + nt * 8 + qc;
            const float2 bv = *(const float2*)&bias[col];
#pragma unroll
            for (int h = 0; h < 2; h++) {
                float v0 = acc[mt][nt][2 * h + 0] + bv.x;
                float v1 = acc[mt][nt][2 * h + 1] + bv.y;
                if (MODE == 1) {
                    v0 = f32_to_tf32(fmaxf(v0, 0.f));
                    v1 = f32_to_tf32(fmaxf(v1, 0.f));
                } else if (MODE == 2) {
                    v0 = f32_to_tf32(v0);
                    v1 = f32_to_tf32(v1);
                }
                float2 o; o.x = v0; o.y = v1;
                *(float2*)&C[(size_t)(row0 + 8 * h) * ldC + col] = o;
            }
        }
    }
}

// ---------------- conversion kernels ---------------------------------------
__global__ void cvt_tf32_kernel(const float* __restrict__ in, float* __restrict__ out, int n4) {
    int i = blockIdx.x * blockDim.x + threadIdx.x;
    if (i < n4) {
        float4 v = ((const float4*)in)[i];
        v.x = f32_to_tf32(v.x); v.y = f32_to_tf32(v.y);
        v.z = f32_to_tf32(v.z); v.w = f32_to_tf32(v.w);
        ((float4*)out)[i] = v;
    }
}

__global__ void cvt_wqkv_kernel(const float* __restrict__ wq, const float* __restrict__ wk,
                                const float* __restrict__ wv, float* __restrict__ out) {
    const int seg = D_MODEL * D_MODEL / 4;
    int i = blockIdx.x * blockDim.x + threadIdx.x;
    if (i < 3 * seg) {
        const float* src = (i < seg) ? wq : (i < 2 * seg) ? wk : wv;
        int j = (i < seg) ? i : (i < 2 * seg) ? i - seg : i - 2 * seg;
        float4 v = ((const float4*)src)[j];
        v.x = f32_to_tf32(v.x); v.y = f32_to_tf32(v.y);
        v.z = f32_to_tf32(v.z); v.w = f32_to_tf32(v.w);
        ((float4*)out)[i] = v;
    }
}

__global__ void bias_concat_kernel(const float* bq, const float* bk, const float* bv,
                                   float* out) {
    int i = blockIdx.x * blockDim.x + threadIdx.x;
    if (i < QKV_LD) {
        float v;
        if (i < D_MODEL) v = bq[i];
        else if (i < 2 * D_MODEL) v = bk[i - D_MODEL];
        else v = bv[i - 2 * D_MODEL];
        out[i] = v;
    }
}

// ---------------- tensor-core local attention -------------------------------
// block = 256 thr (8 warps), 128 q-rows/block, 64 kv/iter, d=64.
#define AQ_PLANE 16384
#define AK_PLANE 8192
#define ATT_SMEM (96 * 1024)

__global__ void __launch_bounds__(256)
attn_mma(const float* __restrict__ QKV, float* __restrict__ Og) {
    extern __shared__ char araw[];
    const uint32_t sb = smem_u32(araw);
    const uint32_t Qs = sb;
    const uint32_t Ks = sb + 32768u;
    const uint32_t Vt = sb + 49152u;
    const uint32_t Ps = sb + 65536u;

    const int tid = threadIdx.x;
    const int lane = tid & 31;
    const int w = tid >> 5;
    const int qt = blockIdx.x;
    const int wnd = blockIdx.y, bh = blockIdx.z;
    const int b = bh >> 4, h = bh & 15;
    const int q0 = wnd * WIN + qt * 128;
    const size_t base = (size_t)b * SEQ * QKV_LD + (size_t)h * DHEAD;
    const size_t obase = (size_t)b * SEQ * D_MODEL + (size_t)h * DHEAD;

    {
        const int r = tid >> 1, half = tid & 1;
        const float* src = QKV + base + (size_t)(q0 + r) * QKV_LD + half * 32;
        const uint32_t drow = Qs + (uint32_t)half * AQ_PLANE + (uint32_t)r * 128u;
#pragma unroll
        for (int u = 0; u < 8; u++) {
            float4 v = *(const float4*)(src + u * 4);
            uint32_t addr = drow + ((uint32_t)(u ^ (r & 7)) << 4);
            asm volatile("st.shared.v4.b32 [%0], {%1,%2,%3,%4};"
                         :: "r"(addr), "r"(__float_as_uint(v.x)), "r"(__float_as_uint(v.y)),
                            "r"(__float_as_uint(v.z)), "r"(__float_as_uint(v.w)) : "memory");
        }
    }

    const int g = lane >> 3, lr = lane & 7;
    const uint32_t aRow = (uint32_t)(w * 16 + (g & 1) * 8 + lr);
    const uint32_t aU = (uint32_t)(g >> 1);
    const uint32_t bU = (uint32_t)(g & 1);
    uint32_t bRow[4];
#pragma unroll
    for (int p = 0; p < 4; p++) bRow[p] = (uint32_t)(p * 16 + (g >> 1) * 8 + lr);

    float acc[8][4];
#pragma unroll
    for (int nt = 0; nt < 8; nt++)
#pragma unroll
        for (int r = 0; r < 4; r++) acc[nt][r] = 0.f;
    float mi0 = -INFINITY, mi1 = -INFINITY, li0 = 0.f, li1 = 0.f;

    const int qrow0 = q0 + w * 16 + (lane >> 2);
    const int qrow1 = qrow0 + 8;
    const int qmax = q0 + w * 16 + 15;

    const int cstart = (wnd == 0) ? 8 : 0;
    const int cend = 2 * qt + 10;

    for (int c = cstart; c < cend; c++) {
        const int kbase = (wnd - 1) * WIN + c * 64;
        __syncthreads();
        if (tid < 128) {
            const int r = tid >> 1, half = tid & 1;
            const float* ks = QKV + base + D_MODEL + (size_t)(kbase + r) * QKV_LD + half * 32;
            const uint32_t drow = Ks + (uint32_t)half * AK_PLANE + (uint32_t)r * 128u;
#pragma unroll
            for (int u = 0; u < 8; u++) {
                float4 v = *(const float4*)(ks + u * 4);
                uint32_t addr = drow + ((uint32_t)(u ^ (r & 7)) << 4);
                asm volatile("st.shared.v4.b32 [%0], {%1,%2,%3,%4};"
                             :: "r"(addr), "r"(__float_as_uint(v.x)), "r"(__float_as_uint(v.y)),
                                "r"(__float_as_uint(v.z)), "r"(__float_as_uint(v.w)) : "memory");
            }
        } else {
            const int t = tid - 128;
            const int r = t >> 1, half = t & 1;
            const float* vs = QKV + base + 2 * D_MODEL + (size_t)(kbase + r) * QKV_LD + half * 32;
            const uint32_t vplane = Vt + (uint32_t)(r >> 5) * AK_PLANE;
            const uint32_t kunit = (uint32_t)((r & 31) >> 2);
            const uint32_t kpos = (uint32_t)(r & 3) * 4u;
#pragma unroll
            for (int u = 0; u < 8; u++) {
                float4 v = *(const float4*)(vs + u * 4);
                const int d0 = half * 32 + u * 4;
#pragma unroll
                for (int e = 0; e < 4; e++) {
                    const uint32_t dr = (uint32_t)(d0 + e);
                    uint32_t addr = vplane + dr * 128u + ((kunit ^ (dr & 7u)) << 4) + kpos;
                    asm volatile("st.shared.b32 [%0], %1;"
                                 :: "r"(addr), "r"(__float_as_uint((&v.x)[e])) : "memory");
                }
            }
        }
        __syncthreads();

        if (kbase > qmax) continue;

        float sc[8][4];
#pragma unroll
        for (int nt = 0; nt < 8; nt++)
#pragma unroll
            for (int r = 0; r < 4; r++) sc[nt][r] = 0.f;
#pragma unroll
        for (int ks = 0; ks < 8; ks++) {
            const uint32_t qpl = Qs + (uint32_t)(ks >> 2) * AQ_PLANE;
            const uint32_t kpl = Ks + (uint32_t)(ks >> 2) * AK_PLANE;
            const uint32_t un = (uint32_t)(ks & 3) * 2u;
            uint32_t a[4], bf[8][2];
            {
                uint32_t addr = qpl + aRow * 128u + (((un + aU) ^ (aRow & 7u)) << 4);
                ldsm_x4(a[0], a[1], a[2], a[3], addr);
            }
#pragma unroll
            for (int p = 0; p < 4; p++) {
                uint32_t addr = kpl + bRow[p] * 128u + (((un + bU) ^ (bRow[p] & 7u)) << 4);
                ldsm_x4(bf[2 * p][0], bf[2 * p][1], bf[2 * p + 1][0], bf[2 * p + 1][1], addr);
            }
#pragma unroll
            for (int nt = 0; nt < 8; nt++) mma8(sc[nt], a, bf[nt]);
        }

        float rm0 = -INFINITY, rm1 = -INFINITY;
#pragma unroll
        for (int nt = 0; nt < 8; nt++) {
            const int col = kbase + nt * 8 + 2 * (lane & 3);
            sc[nt][0] = (col     <= qrow0) ? sc[nt][0] * 0.125f : -INFINITY;
            sc[nt][1] = (col + 1 <= qrow0) ? sc[nt][1] * 0.125f : -INFINITY;
            sc[nt][2] = (col     <= qrow1) ? sc[nt][2] * 0.125f : -INFINITY;
            sc[nt][3] = (col + 1 <= qrow1) ? sc[nt][3] * 0.125f : -INFINITY;
            rm0 = fmaxf(rm0, fmaxf(sc[nt][0], sc[nt][1]));
            rm1 = fmaxf(rm1, fmaxf(sc[nt][2], sc[nt][3]));
        }
#pragma unroll
        for (int o = 1; o <= 2; o <<= 1) {
            rm0 = fmaxf(rm0, __shfl_xor_sync(0xffffffffu, rm0, o));
            rm1 = fmaxf(rm1, __shfl_xor_sync(0xffffffffu, rm1, o));
        }
        const float mn0 = fmaxf(mi0, rm0), mn1 = fmaxf(mi1, rm1);
        const float co0 = (mn0 != -INFINITY) ? __expf(mi0 - mn0) : 0.f;
        const float co1 = (mn1 != -INFINITY) ? __expf(mi1 - mn1) : 0.f;
        float rs0 = 0.f, rs1 = 0.f;
        const uint32_t prow0 = (uint32_t)(w * 16 + (lane >> 2));
#pragma unroll
        for (int nt = 0; nt < 8; nt++) {
            float e0 = (sc[nt][0] != -INFINITY) ? __expf(sc[nt][0] - mn0) : 0.f;
            float e1 = (sc[nt][1] != -INFINITY) ? __expf(sc[nt][1] - mn0) : 0.f;
            float e2 = (sc[nt][2] != -INFINITY) ? __expf(sc[nt][2] - mn1) : 0.f;
            float e3 = (sc[nt][3] != -INFINITY) ? __expf(sc[nt][3] - mn1) : 0.f;
            rs0 += e0 + e1; rs1 += e2 + e3;
            const uint32_t cl = (uint32_t)(nt * 8 + 2 * (lane & 3));
            const uint32_t pl = Ps + (cl >> 5) * AQ_PLANE;
            const uint32_t uoff = (((cl & 31) >> 2) << 4);
            const uint32_t ppos = (cl & 3) * 4u;
            uint32_t a0 = pl + prow0 * 128u + (uoff ^ ((prow0 & 7u) << 4)) + ppos;
            uint32_t a1 = pl + (prow0 + 8u) * 128u + (uoff ^ (((prow0 + 8u) & 7u) << 4)) + ppos;
            asm volatile("st.shared.v2.b32 [%0], {%1,%2};"
                         :: "r"(a0), "r"(__float_as_uint(f32_to_tf32(e0))),
                            "r"(__float_as_uint(f32_to_tf32(e1))) : "memory");
            asm volatile("st.shared.v2.b32 [%0], {%1,%2};"
                         :: "r"(a1), "r"(__float_as_uint(f32_to_tf32(e2))),
                            "r"(__float_as_uint(f32_to_tf32(e3))) : "memory");
        }
#pragma unroll
        for (int o = 1; o <= 2; o <<= 1) {
            rs0 += __shfl_xor_sync(0xffffffffu, rs0, o);
            rs1 += __shfl_xor_sync(0xffffffffu, rs1, o);
        }
        li0 = li0 * co0 + rs0; li1 = li1 * co1 + rs1;
        mi0 = mn0; mi1 = mn1;
#pragma unroll
        for (int nt = 0; nt < 8; nt++) {
            acc[nt][0] *= co0; acc[nt][1] *= co0;
            acc[nt][2] *= co1; acc[nt][3] *= co1;
        }
        __syncwarp();

#pragma unroll
        for (int ks = 0; ks < 8; ks++) {
            const uint32_t ppl = Ps + (uint32_t)(ks >> 2) * AQ_PLANE;
            const uint32_t vpl = Vt + (uint32_t)(ks >> 2) * AK_PLANE;
            const uint32_t un = (uint32_t)(ks & 3) * 2u;
            uint32_t a[4], bf[8][2];
            {
                uint32_t addr = ppl + aRow * 128u + (((un + aU) ^ (aRow & 7u)) << 4);
                ldsm_x4(a[0], a[1], a[2], a[3], addr);
            }
#pragma unroll
            for (int p = 0; p < 4; p++) {
                uint32_t addr = vpl + bRow[p] * 128u + (((un + bU) ^ (bRow[p] & 7u)) << 4);
                ldsm_x4(bf[2 * p][0], bf[2 * p][1], bf[2 * p + 1][0], bf[2 * p + 1][1], addr);
            }
#pragma unroll
            for (int nt = 0; nt < 8; nt++) mma8(acc[nt], a, bf[nt]);
        }
    }

    const float iv0 = 1.f / li0, iv1 = 1.f / li1;
#pragma unroll
    for (int nt = 0; nt < 8; nt++) {
        const int col = nt * 8 + 2 * (lane & 3);
        float2 o0, o1;
        o0.x = acc[nt][0] * iv0; o0.y = acc[nt][1] * iv0;
        o1.x = acc[nt][2] * iv1; o1.y = acc[nt][3] * iv1;
        *(float2*)&Og[obase + (size_t)qrow0 * D_MODEL + col] = o0;
        *(float2*)&Og[obase + (size_t)qrow1 * D_MODEL + col] = o1;
    }
}

// ---------------- fused residual + layernorm --------------------------------
template <int WRITE_T>
__global__ void __launch_bounds__(256)
ln_kernel(const float* __restrict__ A, const float* __restrict__ Badd,
          float aScale, const float* __restrict__ g, const float* __restrict__ be,
          float* __restrict__ out, float* __restrict__ out_t) {
    const int row = blockIdx.x;
    const int tid = threadIdx.x;
    const size_t off = (size_t)row * D_MODEL;

    float y[4];
    float s = 0.f, s2 = 0.f;
#pragma unroll
    for (int u = 0; u < 4; u++) {
        const int c = tid + u * 256;
        float v = aScale * A[off + c];
        if (Badd) v += Badd[off + c];
        y[u] = v;
        s += v;
        s2 += v * v;
    }
#pragma unroll
    for (int o = 16; o; o >>= 1) {
        s  += __shfl_xor_sync(0xffffffffu, s, o);
        s2 += __shfl_xor_sync(0xffffffffu, s2, o);
    }
    __shared__ float rs[8], rs2[8];
    __shared__ float sh_mu, sh_rstd;
    const int wid = tid >> 5, lane = tid & 31;
    if (lane == 0) { rs[wid] = s; rs2[wid] = s2; }
    __syncthreads();
    if (tid == 0) {
        float S = 0.f, S2 = 0.f;
#pragma unroll
        for (int i = 0; i < 8; i++) { S += rs[i]; S2 += rs2[i]; }
        const float mu = S * (1.f / D_MODEL);
        const float var = S2 * (1.f / D_MODEL) - mu * mu;
        sh_mu = mu;
        sh_rstd = rsqrtf(var + LN_EPS);
    }
    __syncthreads();
    const float mu = sh_mu, rstd = sh_rstd;
#pragma unroll
    for (int u = 0; u < 4; u++) {
        const int c = tid + u * 256;
        const float v = (y[u] - mu) * rstd * g[c] + be[c];
        out[off + c] = v;
        if (WRITE_T) out_t[off + c] = f32_to_tf32(v);
    }
}

// ---------------- launch ----------------------------------------------------
extern "C" void kernel_launch(void* const* d_in, const int* in_sizes, int n_in,
                              void* d_out, int out_size) {
    const float* src = (const float*)d_in[0];
    const float* wq = (const float*)d_in[1];  const float* bq = (const float*)d_in[2];
    const float* wk = (const float*)d_in[3];  const float* bk = (const float*)d_in[4];
    const float* wv = (const float*)d_in[5];  const float* bv = (const float*)d_in[6];
    const float* w1 = (const float*)d_in[7];  const float* b1 = (const float*)d_in[8];
    const float* w2 = (const float*)d_in[9];  const float* b2 = (const float*)d_in[10];
    const float* g1 = (const float*)d_in[11]; const float* be1 = (const float*)d_in[12];
    const float* g2 = (const float*)d_in[13]; const float* be2 = (const float*)d_in[14];
    float* out = (float*)d_out;

    void *psrct, *pwqkv, *pbqkv, *pqkv, *pattn, *px1, *px1t, *pw1t, *pffnt, *pw2t, *pf2;
    cudaGetSymbolAddress(&psrct, g_srct);
    cudaGetSymbolAddress(&pwqkv, g_wqkv);
    cudaGetSymbolAddress(&pbqkv, g_bqkv);
    cudaGetSymbolAddress(&pqkv,  g_qkv);
    cudaGetSymbolAddress(&pattn, g_attn);
    cudaGetSymbolAddress(&px1,   g_x1);
    cudaGetSymbolAddress(&px1t,  g_x1t);
    cudaGetSymbolAddress(&pw1t,  g_w1t);
    cudaGetSymbolAddress(&pffnt, g_ffnt);
    cudaGetSymbolAddress(&pw2t,  g_w2t);
    cudaGetSymbolAddress(&pf2,   g_f2);

    cudaFuncSetAttribute(gemm_mma<0>, cudaFuncAttributeMaxDynamicSharedMemorySize, GEMM_SMEM);
    cudaFuncSetAttribute(gemm_mma<1>, cudaFuncAttributeMaxDynamicSharedMemorySize, GEMM_SMEM);
    cudaFuncSetAttribute(gemm_mma<2>, cudaFuncAttributeMaxDynamicSharedMemorySize, GEMM_SMEM);
    cudaFuncSetAttribute(attn_mma, cudaFuncAttributeMaxDynamicSharedMemorySize, ATT_SMEM);

    {   // [0] src -> tf32
        int n4 = MROWS * D_MODEL / 4;
        cvt_tf32_kernel<<<(n4 + 255) / 256, 256>>>(src, (float*)psrct, n4);
    }
    {   // [1] wq|wk|wv -> tf32 concat
        int n4 = 3 * D_MODEL * D_MODEL / 4;
        cvt_wqkv_kernel<<<(n4 + 255) / 256, 256>>>(wq, wk, wv, (float*)pwqkv);
    }
    // [2] bias concat
    bias_concat_kernel<<<(QKV_LD + 255) / 256, 256>>>(bq, bk, bv, (float*)pbqkv);
    {   // [3] w1 -> tf32
        int n4 = DFF * D_MODEL / 4;
        cvt_tf32_kernel<<<(n4 + 255) / 256, 256>>>(w1, (float*)pw1t, n4);
    }
    {   // [4] fused QKV GEMM (epilogue rounds to tf32 for attention)
        dim3 grid(QKV_LD / 128, MROWS / 128);
        gemm_mma<2><<<grid, 128, GEMM_SMEM>>>((const float*)psrct, (const float*)pwqkv,
                                              (const float*)pbqkv, (float*)pqkv,
                                              D_MODEL, QKV_LD);
    }
    {   // [5] tensor-core local attention
        dim3 gAttn(WIN / 128, NWIN, BATCH * NHEAD);
        attn_mma<<<gAttn, 256, ATT_SMEM>>>((const float*)pqkv, (float*)pattn);
    }
    {   // [6] w2 -> tf32
        int n4 = D_MODEL * DFF / 4;
        cvt_tf32_kernel<<<(n4 + 255) / 256, 256>>>(w2, (float*)pw2t, n4);
    }
    // [7] LN1
    ln_kernel<1><<<MROWS, 256>>>((const float*)pattn, nullptr, 2.0f, g1, be1,
                                 (float*)px1, (float*)px1t);
    {   // [8] FFN1
        dim3 grid(DFF / 128, MROWS / 128);
        gemm_mma<1><<<grid, 128, GEMM_SMEM>>>((const float*)px1t, (const float*)pw1t,
                                              b1, (float*)pffnt, D_MODEL, DFF);
    }
    {   // [9] FFN2
        dim3 grid(D_MODEL / 128, MROWS / 128);
        gemm_mma<0><<<grid, 128, GEMM_SMEM>>>((const float*)pffnt, (const float*)pw2t,
                                              b2, (float*)pf2, DFF, D_MODEL);
    }
    // [10] LN2
    ln_kernel<0><<<MROWS, 256>>>((const float*)px1, (const float*)pf2, 1.0f, g2, be2,
                                 out, nullptr);
}